// round 9
// baseline (speedup 1.0000x reference)
#include <cuda_runtime.h>

#define NQ1 10001
#define NC1 301
#define ND1 200
#define NA1 20002

// ---- device scratch (static globals: no runtime allocation) ----
__device__ float g_C23 [128*256];   // [W2|W3] row-major (GEMM B operand)
__device__ float g_W45a[128*256];   // [W4[128:],W5[128:]]
__device__ float g_b45 [256];
__device__ float g_b23 [256];       // [b2|b3]
__device__ float g_cst23[256];      // b1@C23 + [b2|b3]
__device__ float g_G   [512*256];   // W1 @ C23
__device__ float g_TQ  [NQ1*256];
__device__ float g_TC  [NC1*256];
__device__ float g_TS1 [ND1*256];
__device__ float g_TD1 [ND1*256];
__device__ float g_TA45[NA1*256];
__device__ float g_TA6 [NA1*128];
__device__ float g_TS6 [ND1*128];
__device__ float g_TD6 [ND1*128];

__device__ __forceinline__ float sigm(float x) { return 1.f / (1.f + __expf(-x)); }
__device__ __forceinline__ float tanh_fast(float x) {
    float y; asm("tanh.approx.f32 %0, %1;" : "=f"(y) : "f"(x)); return y;
}

// ---------------------------------------------------------------------------
__global__ void prep_concat(const float* __restrict__ W2, const float* __restrict__ W3,
                            const float* __restrict__ W4, const float* __restrict__ W5,
                            const float* __restrict__ b2, const float* __restrict__ b3,
                            const float* __restrict__ b4, const float* __restrict__ b5)
{
    int e = blockIdx.x * 256 + threadIdx.x;
    if (e < 128*256) {
        int i = e >> 8, j = e & 255;
        g_C23 [e] = (j < 128) ? W2[i*128 + j]       : W3[i*128 + (j-128)];
        g_W45a[e] = (j < 128) ? W4[(128+i)*128 + j] : W5[(128+i)*128 + (j-128)];
    }
    if (e < 256) {
        g_b45[e] = (e < 128) ? b4[e] : b5[e-128];
        g_b23[e] = (e < 128) ? b2[e] : b3[e-128];
    }
}

// ---------------------------------------------------------------------------
// batched table GEMM: C[M,N] = A[M,128]@B[128,N] (+bias)
// 256 thr, 64 rows/block, 8 rows/warp (2x arithmetic intensity vs R6).
// ---------------------------------------------------------------------------
struct GDesc { const float *A, *B, *bias; float *C; int M, N; };
struct GBatch { GDesc g[6]; int start[7]; int n; };

__global__ void gemm_batched(GBatch bt)
{
    __shared__ float As[64*128];
    int gi = 0;
    while (gi < bt.n - 1 && (int)blockIdx.x >= bt.start[gi+1]) gi++;
    const GDesc d = bt.g[gi];
    const int blk = blockIdx.x - bt.start[gi];

    const int tid = threadIdx.x, w = tid >> 5, lane = tid & 31;
    const int row0 = blk * 64;
    for (int e = tid; e < 8192; e += 256) {
        int rr = e >> 7, ii = e & 127, gr = row0 + rr;
        As[e] = (gr < d.M) ? d.A[gr*128 + ii] : 0.f;
    }
    __syncthreads();
    const int r0 = w * 8;
    for (int jo = 0; jo < d.N; jo += 128) {
        const int j = jo + lane * 4;
        float acc[8][4] = {};
        const float* Bp = d.B + j;
        #pragma unroll 2
        for (int i = 0; i < 128; i++) {
            float4 bb = *reinterpret_cast<const float4*>(Bp + i*d.N);
            #pragma unroll
            for (int rr = 0; rr < 8; rr++) {
                float av = As[(r0 + rr)*128 + i];
                acc[rr][0] += av*bb.x; acc[rr][1] += av*bb.y;
                acc[rr][2] += av*bb.z; acc[rr][3] += av*bb.w;
            }
        }
        float4 bv = d.bias ? *reinterpret_cast<const float4*>(d.bias + j)
                           : make_float4(0.f, 0.f, 0.f, 0.f);
        #pragma unroll
        for (int rr = 0; rr < 8; rr++) {
            int row = row0 + r0 + rr;
            if (row < d.M) {
                float4 o;
                o.x = acc[rr][0]+bv.x; o.y = acc[rr][1]+bv.y;
                o.z = acc[rr][2]+bv.z; o.w = acc[rr][3]+bv.w;
                *reinterpret_cast<float4*>(d.C + row*d.N + j) = o;
            }
        }
    }
}

// ---------------------------------------------------------------------------
// scan: one CTA per batch row (128 CTAs, 512 threads, split-K halves).
// col c = t&255, half h = t>>8. w45 half-column in 64 regs.
// Logits pipelined into warps 12-14 via shuffle (step stp-1 during stage 2).
// ---------------------------------------------------------------------------
#define C23T_STRIDE 132
#define SCAN_SMEM_FLOATS (256*132 + 128*132 + 1280 + 128 + 128 + 256 + 256 + 512 + 512 + 512)
#define SCAN_SMEM_BYTES  ((SCAN_SMEM_FLOATS + 5*512) * 4)

__global__ void __launch_bounds__(512, 1)
scan_kernel(const int* __restrict__ qi_, const int* __restrict__ ci_,
            const int* __restrict__ si_, const int* __restrict__ di_,
            const int* __restrict__ ai_,
            const float* __restrict__ knowledge,
            const float* __restrict__ W2, const float* __restrict__ W3,
            const float* __restrict__ W4, const float* __restrict__ W5,
            const float* __restrict__ W6,
            const float* __restrict__ Wf, const float* __restrict__ bf,
            float* __restrict__ out)
{
    extern __shared__ float sm[];
    float* C23t = sm;                    // [col][i], stride 132, col<256
    float* W6t  = C23t + 256*132;        // [col][i], stride 132, col<128
    float* Wfs  = W6t + 128*132;         // 10x128 ([o][i])
    float* kvec = Wfs + 1280;            // 128
    float* sdf  = kvec + 128;            // 128
    float* zb   = sdf + 128;             // 256
    float* pb   = zb + 256;              // 256
    float* zp   = pb + 256;              // 512
    float* g6p  = zp + 512;              // 512
    float* pp   = g6p + 512;             // 512
    int*   idxs = (int*)(pp + 512);      // 5*512

    const int b = blockIdx.x, t = threadIdx.x;
    const int c = t & 255;               // column
    const int h = t >> 8;                // half (0/1)
    const int base = h * 64;

    // fills
    for (int e = t; e < 128*256; e += 512) {
        int i = e >> 8, j = e & 255;
        float v = (j < 128) ? W2[i*128 + j] : W3[i*128 + (j-128)];
        C23t[j*C23T_STRIDE + i] = v;
    }
    for (int e = t; e < 128*128; e += 512) {
        int i = e >> 7, cc = e & 127;
        W6t[cc*C23T_STRIDE + i] = W6[i*128 + cc];
    }
    for (int e = t; e < 1280; e += 512) { int o = e >> 7, i = e & 127; Wfs[e] = Wf[i*10 + o]; }
    if (t < 128) kvec[t] = knowledge[t];
    for (int e = t; e < 512; e += 512) {
        int g = b*512 + e;
        idxs[e]        = qi_[g];
        idxs[512 + e]  = ci_[g];
        idxs[1024 + e] = si_[g];
        idxs[1536 + e] = di_[g];
        idxs[2048 + e] = ai_[g];
    }

    // register-resident [W4s|W5s] half-column (64 regs, fully unrolled)
    float w45r[64];
    {
        const float* Ws = (c < 128) ? W4 : W5;
        const int cc = c & 127;
        #pragma unroll
        for (int j = 0; j < 64; j++) w45r[j] = Ws[(base + j)*128 + cc];
    }
    // logits assignment: warps 12-14 (t in [384,480)), u = t-384 in [0,80)
    const int u = t - 384;
    const bool logit_thread = (t >= 384 && t < 480);
    const int lo = u >> 3;                 // output 0..9 (valid when u<80)
    const int lseg = (u & 7) << 4;         // 16-elem segment
    const float bfreg = (logit_thread && (u & 7) == 0) ? bf[lo] : 0.f;
    __syncthreads();

    const bool low = (t < 128);

    // prefetch step-0 streams (held by t<256 / t<128)
    float xq = 0.f, xc = 0.f, xs = 0.f, xd = 0.f, a45p = 0.f;
    float r6a = 0.f, r6s = 0.f, r6d = 0.f;
    if (t < 256) {
        int q0 = idxs[0], c0 = idxs[512], s0 = idxs[1024], d0 = idxs[1536], a0 = idxs[2048];
        xq = g_TQ[q0*256 + t];  xc = g_TC[c0*256 + t];
        xs = g_TS1[s0*256 + t]; xd = g_TD1[d0*256 + t];
        a45p = g_TA45[a0*256 + t];
        if (low) { r6a = g_TA6[a0*128 + t]; r6s = g_TS6[s0*128 + t]; r6d = g_TD6[d0*128 + t]; }
    }

    const float* wc  = C23t + c*C23T_STRIDE + base;
    const float* w6p = W6t + (t & 127)*C23T_STRIDE + ((t >> 7) * 32);
    const int goff   = (t >> 7) * 32;
    float* outp = out + b * 5120;
    float greg = 0.f, kold = 0.f;

    for (int stp = 0; stp < 512; stp++) {
        const float x23c = (xq + xc) + (xs + xd);
        const float a45c = a45p;
        const float r6c  = (r6a + r6s) + r6d;

        if (t < 256 && stp + 1 < 512) {
            int q1 = idxs[stp+1],      c1 = idxs[512+stp+1], s1 = idxs[1024+stp+1],
                d1 = idxs[1536+stp+1], a1 = idxs[2048+stp+1];
            xq = g_TQ[q1*256 + t];  xc = g_TC[c1*256 + t];
            xs = g_TS1[s1*256 + t]; xd = g_TD1[d1*256 + t];
            a45p = g_TA45[a1*256 + t];
            if (low) { r6a = g_TA6[a1*128 + t]; r6s = g_TS6[s1*128 + t]; r6d = g_TD6[d1*128 + t]; }
        }

        // ---- S1: zp partial (64 FMA) + g6 quarter partial (32 FMA) ----
        float A0=0.f,A1=0.f,A2=0.f,A3=0.f;
        #pragma unroll
        for (int i = 0; i < 64; i += 4) {
            float4 k4 = *reinterpret_cast<const float4*>(kvec + base + i);
            float4 w4 = *reinterpret_cast<const float4*>(wc + i);
            A0 += k4.x * w4.x; A1 += k4.y * w4.y;
            A2 += k4.z * w4.z; A3 += k4.w * w4.w;
        }
        float G0=0.f,G1=0.f,G2=0.f,G3=0.f;
        #pragma unroll
        for (int i = 0; i < 32; i += 4) {
            float4 k4 = *reinterpret_cast<const float4*>(kvec + goff + i);
            float4 w4 = *reinterpret_cast<const float4*>(w6p + i);
            G0 += k4.x * w4.x; G1 += k4.y * w4.y;
            G2 += k4.z * w4.z; G3 += k4.w * w4.w;
        }
        zp[t]  = (A0+A1)+(A2+A3);
        g6p[t] = (G0+G1)+(G2+G3);
        __syncthreads();   // B1

        // ---- S2: zb combine (t<256) ; pipelined logits for step stp-1 (warps 12-14) ----
        if (t < 256) {
            zb[t] = x23c - (zp[t] + zp[256 + t]);
        } else if (logit_thread && stp > 0) {
            const float* wf = Wfs + lo*128 + lseg;
            const float* kk = kvec + lseg;
            float acc = 0.f;
            #pragma unroll
            for (int i = 0; i < 16; i += 4) {
                float4 k4 = *reinterpret_cast<const float4*>(kk + i);
                float4 wv = *reinterpret_cast<const float4*>(wf + i);
                acc += k4.x*wv.x + k4.y*wv.y + k4.z*wv.z + k4.w*wv.w;
            }
            acc += __shfl_down_sync(0xFFFFFFFFu, acc, 4, 8);
            acc += __shfl_down_sync(0xFFFFFFFFu, acc, 2, 8);
            acc += __shfl_down_sync(0xFFFFFFFFu, acc, 1, 8);
            if ((u & 7) == 0 && u < 80)
                outp[(stp-1)*10 + lo] = sigm(acc + bfreg);
        }
        __syncthreads();   // B2

        // ---- S3 (t<128): SDFt + gate ----
        if (low) {
            sdf[t] = sigm(zb[t]) * tanh_fast(zb[128 + t]);
            greg = sigm(g6p[t] + g6p[128 + t] + g6p[256 + t] + g6p[384 + t] + r6c);
            kold = kvec[t];
        }
        __syncthreads();   // B3

        // ---- S4: P partial (64 FMA, w45r in regs) ----
        float P0=0.f,P1=0.f,P2=0.f,P3=0.f;
        #pragma unroll
        for (int i = 0; i < 64; i += 4) {
            float4 s4 = *reinterpret_cast<const float4*>(sdf + base + i);
            P0 += s4.x * w45r[i+0];
            P1 += s4.y * w45r[i+1];
            P2 += s4.z * w45r[i+2];
            P3 += s4.w * w45r[i+3];
        }
        pp[t] = (P0+P1)+(P2+P3);
        __syncthreads();   // B4

        // ---- S5 (t<256): pb combine ----
        if (t < 256) pb[t] = pp[t] + pp[256 + t] + a45c;
        __syncthreads();   // B5

        // ---- S6 (t<128): PKAt, k update ----
        if (low) {
            float pka = sigm(pb[t]) * tanh_fast(pb[128 + t]);
            kvec[t] = greg * kold + (1.f - greg) * pka;
        }
        __syncthreads();   // B6
    }

    // epilogue: logits for final step (511)
    if (logit_thread) {
        const float* wf = Wfs + lo*128 + lseg;
        const float* kk = kvec + lseg;
        float acc = 0.f;
        #pragma unroll
        for (int i = 0; i < 16; i += 4) {
            float4 k4 = *reinterpret_cast<const float4*>(kk + i);
            float4 wv = *reinterpret_cast<const float4*>(wf + i);
            acc += k4.x*wv.x + k4.y*wv.y + k4.z*wv.z + k4.w*wv.w;
        }
        acc += __shfl_down_sync(0xFFFFFFFFu, acc, 4, 8);
        acc += __shfl_down_sync(0xFFFFFFFFu, acc, 2, 8);
        acc += __shfl_down_sync(0xFFFFFFFFu, acc, 1, 8);
        if ((u & 7) == 0 && u < 80)
            outp[511*10 + lo] = sigm(acc + bfreg);
    }
}

// ---------------------------------------------------------------------------
extern "C" void kernel_launch(void* const* d_in, const int* in_sizes, int n_in,
                              void* d_out, int out_size)
{
    const int* qi = (const int*)d_in[0];
    const int* ci = (const int*)d_in[1];
    const int* si = (const int*)d_in[2];
    const int* di = (const int*)d_in[3];
    const int* ai = (const int*)d_in[4];
    const float* knowledge = (const float*)d_in[9];
    const float* q_tab  = (const float*)d_in[10];
    const float* c_tab  = (const float*)d_in[11];
    const float* sd_tab = (const float*)d_in[12];
    const float* qd_tab = (const float*)d_in[13];
    const float* a_tab  = (const float*)d_in[14];
    const float* W1 = (const float*)d_in[15]; const float* b1 = (const float*)d_in[16];
    const float* W2 = (const float*)d_in[17]; const float* b2 = (const float*)d_in[18];
    const float* W3 = (const float*)d_in[19]; const float* b3 = (const float*)d_in[20];
    const float* W4 = (const float*)d_in[21]; const float* b4 = (const float*)d_in[22];
    const float* W5 = (const float*)d_in[23]; const float* b5 = (const float*)d_in[24];
    const float* W6 = (const float*)d_in[25]; const float* b6 = (const float*)d_in[26];
    const float* Wf = (const float*)d_in[27]; const float* bf = (const float*)d_in[28];
    float* out = (float*)d_out;

    float *pC23, *pW45a, *pb45, *pb23, *pcst, *pG, *pTQ, *pTC, *pTS1, *pTD1, *pTA45, *pTA6, *pTS6, *pTD6;
    cudaGetSymbolAddress((void**)&pC23,  g_C23);
    cudaGetSymbolAddress((void**)&pW45a, g_W45a);
    cudaGetSymbolAddress((void**)&pb45,  g_b45);
    cudaGetSymbolAddress((void**)&pb23,  g_b23);
    cudaGetSymbolAddress((void**)&pcst,  g_cst23);
    cudaGetSymbolAddress((void**)&pG,    g_G);
    cudaGetSymbolAddress((void**)&pTQ,   g_TQ);
    cudaGetSymbolAddress((void**)&pTC,   g_TC);
    cudaGetSymbolAddress((void**)&pTS1,  g_TS1);
    cudaGetSymbolAddress((void**)&pTD1,  g_TD1);
    cudaGetSymbolAddress((void**)&pTA45, g_TA45);
    cudaGetSymbolAddress((void**)&pTA6,  g_TA6);
    cudaGetSymbolAddress((void**)&pTS6,  g_TS6);
    cudaGetSymbolAddress((void**)&pTD6,  g_TD6);

    // launch 0: prep
    prep_concat<<<128, 256>>>(W2, W3, W4, W5, b2, b3, b4, b5);

    // launch 1: batch A (needs only prep): G, cst23, TA45, TA6, TS6, TD6
    {
        GBatch bt; bt.n = 6;
        bt.g[0] = { W1,     pC23,         nullptr, pG,    512, 256 };
        bt.g[1] = { b1,     pC23,         pb23,    pcst,  1,   256 };
        bt.g[2] = { a_tab,  pW45a,        pb45,    pTA45, NA1, 256 };
        bt.g[3] = { a_tab,  W6 + 128*128, b6,      pTA6,  NA1, 128 };
        bt.g[4] = { sd_tab, W6 + 256*128, nullptr, pTS6,  ND1, 128 };
        bt.g[5] = { qd_tab, W6 + 384*128, nullptr, pTD6,  ND1, 128 };
        int s = 0; bt.start[0] = 0;
        for (int i = 0; i < 6; i++) { s += (bt.g[i].M + 63) / 64; bt.start[i+1] = s; }
        gemm_batched<<<s, 256>>>(bt);
    }
    // launch 2: batch B (needs G/cst): TQ, TC, TS1, TD1
    {
        GBatch bt; bt.n = 4;
        bt.g[0] = { q_tab,  pG,           pcst,    pTQ,  NQ1, 256 };
        bt.g[1] = { c_tab,  pG + 128*256, nullptr, pTC,  NC1, 256 };
        bt.g[2] = { sd_tab, pG + 256*256, nullptr, pTS1, ND1, 256 };
        bt.g[3] = { qd_tab, pG + 384*256, nullptr, pTD1, ND1, 256 };
        int s = 0; bt.start[0] = 0;
        for (int i = 0; i < 4; i++) { s += (bt.g[i].M + 63) / 64; bt.start[i+1] = s; }
        gemm_batched<<<s, 256>>>(bt);
    }

    // launch 3: scan (profiled launch)
    cudaFuncSetAttribute(scan_kernel, cudaFuncAttributeMaxDynamicSharedMemorySize, SCAN_SMEM_BYTES);
    scan_kernel<<<128, 512, SCAN_SMEM_BYTES>>>(qi, ci, si, di, ai, knowledge,
                                               W2, W3, W4, W5, W6, Wf, bf, out);
}